// round 4
// baseline (speedup 1.0000x reference)
#include <cuda_runtime.h>
#include <cuda_bf16.h>
#include <cstdint>

// Problem constants (shapes are fixed by the dataset)
#define MAXN 50000
#define MAXE 800000

// ---------------- scratch (device globals: no allocation allowed) ----------
__device__ __align__(16) int   g_deg[MAXN];
__device__ __align__(16) int   g_cursor[MAXN];
__device__ __align__(16) int   g_rowptr[MAXN + 2];
__device__ __align__(16) float g_dis[MAXN];
__device__ __align__(16) int   g_col[MAXE];
__device__ __align__(16) float g_w[MAXE];
__device__ __align__(16) float g_h1[(size_t)MAXN * 128];
__device__ __align__(16) float g_h2[(size_t)MAXN * 128];

// buffer selectors (resolved in device code)
__device__ __forceinline__ const float* buf_in(int sel) {
    return sel == 0 ? g_h1 : g_h2;
}
__device__ __forceinline__ float* buf_out(int sel) {
    return sel == 0 ? g_h1 : g_h2;
}

// ---------------- preprocessing kernels ------------------------------------
__global__ void k_zero(int n) {
    int i = blockIdx.x * blockDim.x + threadIdx.x;
    if (i < n) { g_deg[i] = 0; g_cursor[i] = 0; }
}

// edge_index is INT32 (JAX x64 disabled coerces jnp.int64 -> int32).
__global__ void k_count(const int* __restrict__ dst, int E, int n) {
    int i = blockIdx.x * blockDim.x + threadIdx.x;
    if (i < E) {
        unsigned d = (unsigned)dst[i];
        if (d < (unsigned)n) atomicAdd(&g_deg[d], 1);
    }
}

__global__ void k_dis(int n) {
    int i = blockIdx.x * blockDim.x + threadIdx.x;
    if (i < n) g_dis[i] = rsqrtf((float)(g_deg[i] + 1));  // +1 self loop
}

// single-block exclusive scan over g_deg -> g_rowptr (n <= 50000)
__global__ void k_scan(int n) {
    __shared__ int ssum[1024];
    int tid = threadIdx.x;
    int chunk = (n + 1023) / 1024;
    int start = tid * chunk;
    int end = min(start + chunk, n);
    int s = 0;
    for (int i = start; i < end; i++) s += g_deg[i];
    ssum[tid] = s;
    __syncthreads();
    for (int off = 1; off < 1024; off <<= 1) {
        int v = 0;
        if (tid >= off) v = ssum[tid - off];
        __syncthreads();
        ssum[tid] += v;
        __syncthreads();
    }
    int base = (tid == 0) ? 0 : ssum[tid - 1];
    for (int i = start; i < end; i++) { g_rowptr[i] = base; base += g_deg[i]; }
    if (tid == 1023) g_rowptr[n] = ssum[1023];
}

__global__ void k_fill(const int* __restrict__ src,
                       const int* __restrict__ dst, int E, int n) {
    int i = blockIdx.x * blockDim.x + threadIdx.x;
    if (i < E) {
        unsigned s = (unsigned)src[i];
        unsigned d = (unsigned)dst[i];
        if (s < (unsigned)n && d < (unsigned)n) {
            int pos = g_rowptr[d] + atomicAdd(&g_cursor[d], 1);
            g_col[pos] = (int)s;
            g_w[pos] = g_dis[s] * g_dis[d];
        }
    }
}

// ---------------- aggregation: one warp per node ----------------------------
// out[i] = dis[i]^2 * in[i] + sum_{j in N(i)} w_j * in[col_j]

// 128-wide: reads g_h2, writes g_h1
__global__ void k_agg128(int n) {
    int warp = (blockIdx.x * blockDim.x + threadIdx.x) >> 5;
    int lane = threadIdx.x & 31;
    if (warp >= n) return;
    const float* in = g_h2;
    float* out = g_h1;
    float ds = g_dis[warp];
    float self = ds * ds;
    float4 v = ((const float4*)(in + (size_t)warp * 128))[lane];
    float4 acc = make_float4(self * v.x, self * v.y, self * v.z, self * v.w);
    int beg = g_rowptr[warp], end = g_rowptr[warp + 1];
    for (int j = beg; j < end; j++) {
        int s = g_col[j];
        float w = g_w[j];
        float4 u = ((const float4*)(in + (size_t)s * 128))[lane];
        acc.x += w * u.x; acc.y += w * u.y; acc.z += w * u.z; acc.w += w * u.w;
    }
    ((float4*)(out + (size_t)warp * 128))[lane] = acc;
}

// 64-wide, first layer: reads external x, writes g_h1
__global__ void k_agg64_first(const float* __restrict__ in, int n) {
    int warp = (blockIdx.x * blockDim.x + threadIdx.x) >> 5;
    int lane = threadIdx.x & 31;
    if (warp >= n) return;
    float* out = g_h1;
    float ds = g_dis[warp];
    float self = ds * ds;
    float2 v = ((const float2*)(in + (size_t)warp * 64))[lane];
    float2 acc = make_float2(self * v.x, self * v.y);
    int beg = g_rowptr[warp], end = g_rowptr[warp + 1];
    for (int j = beg; j < end; j++) {
        int s = g_col[j];
        float w = g_w[j];
        float2 u = ((const float2*)(in + (size_t)s * 64))[lane];
        acc.x += w * u.x; acc.y += w * u.y;
    }
    ((float2*)(out + (size_t)warp * 64))[lane] = acc;
}

// 64-wide, last layer: reads g_h1, writes external out, adds bias
__global__ void k_agg64_last(float* __restrict__ out,
                             const float* __restrict__ bias, int n) {
    int warp = (blockIdx.x * blockDim.x + threadIdx.x) >> 5;
    int lane = threadIdx.x & 31;
    if (warp >= n) return;
    const float* in = g_h1;
    float ds = g_dis[warp];
    float self = ds * ds;
    float2 v = ((const float2*)(in + (size_t)warp * 64))[lane];
    float2 acc = make_float2(self * v.x, self * v.y);
    int beg = g_rowptr[warp], end = g_rowptr[warp + 1];
    for (int j = beg; j < end; j++) {
        int s = g_col[j];
        float w = g_w[j];
        float2 u = ((const float2*)(in + (size_t)s * 64))[lane];
        acc.x += w * u.x; acc.y += w * u.y;
    }
    acc.x += bias[lane * 2];
    acc.y += bias[lane * 2 + 1];
    ((float2*)(out + (size_t)warp * 64))[lane] = acc;
}

// ---------------- dense GEMM: Y = X[n,IN] @ W[IN,OUT] (+bias)(+relu) --------
// X/Y are internal buffers chosen by selector (0 = g_h1, 1 = g_h2).
template <int IN, int OUT, bool BIAS, bool RELU>
__global__ void k_gemm(int insel, int outsel,
                       const float* __restrict__ Wm,
                       const float* __restrict__ bias, int n) {
    constexpr int TM = 64;
    constexpr int G = 256 / OUT;   // 2 (OUT=128) or 4 (OUT=64)
    constexpr int NR = TM / G;     // rows per thread: 32 or 16
    constexpr int LD = IN + 1;     // pad to dodge bank conflicts
    __shared__ float Xs[TM * LD];

    const float* X = buf_in(insel);
    float* Y = buf_out(outsel);

    int block_row = blockIdx.x * TM;
    for (int idx = threadIdx.x; idx < TM * IN; idx += 256) {
        int r = idx / IN, k = idx % IN;
        int gr = block_row + r;
        Xs[r * LD + k] = (gr < n) ? X[(size_t)gr * IN + k] : 0.f;
    }
    __syncthreads();

    int col = threadIdx.x % OUT;
    int rg = threadIdx.x / OUT;
    float acc[NR];
#pragma unroll
    for (int i = 0; i < NR; i++) acc[i] = 0.f;

#pragma unroll 4
    for (int k = 0; k < IN; k++) {
        float wv = __ldg(&Wm[k * OUT + col]);
#pragma unroll
        for (int i = 0; i < NR; i++)
            acc[i] += Xs[(rg + i * G) * LD + k] * wv;
    }

    float b = BIAS ? __ldg(&bias[col]) : 0.f;
#pragma unroll
    for (int i = 0; i < NR; i++) {
        int r = block_row + rg + i * G;
        if (r < n) {
            float v = acc[i] + b;
            if (RELU) v = fmaxf(v, 0.f);
            Y[(size_t)r * OUT + col] = v;
        }
    }
}

// ---------------- launch ----------------------------------------------------
extern "C" void kernel_launch(void* const* d_in, const int* in_sizes, int n_in,
                              void* d_out, int out_size) {
    const float* x  = (const float*)d_in[0];
    const int*   ei = (const int*)d_in[1];   // int32! (JAX x64 disabled)
    const float* W1 = (const float*)d_in[2];
    const float* b1 = (const float*)d_in[3];
    const float* W2 = (const float*)d_in[4];
    const float* b2 = (const float*)d_in[5];
    const float* W3 = (const float*)d_in[6];
    const float* b3 = (const float*)d_in[7];
    float* out = (float*)d_out;

    const int n = in_sizes[0] / 64;   // 50000
    const int E = in_sizes[1] / 2;    // 800000
    const int* src = ei;
    const int* dst = ei + E;

    const int T = 256;
    // --- build CSR + normalization ---
    k_zero<<<(n + T - 1) / T, T>>>(n);
    k_count<<<(E + T - 1) / T, T>>>(dst, E, n);
    k_dis<<<(n + T - 1) / T, T>>>(n);
    k_scan<<<1, 1024>>>(n);
    k_fill<<<(E + T - 1) / T, T>>>(src, dst, E, n);

    const int aggGrid = (n + 7) / 8;  // 8 warps per block (256 threads)

    // Layer 1: (A x)[64] @ W1 -> relu -> g_h2[128]
    k_agg64_first<<<aggGrid, T>>>(x, n);                                  // x -> g_h1
    k_gemm<64, 128, true, true><<<(n + 63) / 64, T>>>(0, 1, W1, b1, n);   // g_h1 -> g_h2

    // Layer 2: (A g_h2)[128] @ W2 -> relu -> g_h2[128]
    k_agg128<<<aggGrid, T>>>(n);                                          // g_h2 -> g_h1
    k_gemm<128, 128, true, true><<<(n + 63) / 64, T>>>(0, 1, W2, b2, n);  // g_h1 -> g_h2

    // Layer 3: (g_h2 @ W3)[64] -> aggregate -> + b3 -> out
    k_gemm<128, 64, false, false><<<(n + 63) / 64, T>>>(1, 0, W3, nullptr, n); // g_h2 -> g_h1
    k_agg64_last<<<aggGrid, T>>>(out, b3, n);                             // g_h1 -> out
}

// round 5
// speedup vs baseline: 1.4307x; 1.4307x over previous
#include <cuda_runtime.h>
#include <cuda_bf16.h>
#include <cstdint>

#define MAXN 50000
#define MAXE 800000
#define SCAN_B 256
#define MAX_SCAN_BLOCKS ((MAXN + SCAN_B - 1) / SCAN_B)   // 196

// ---------------- scratch (device globals: no allocation allowed) ----------
__device__ __align__(16) int   g_deg[MAXN];
__device__ __align__(16) int   g_cursor[MAXN];
__device__ __align__(16) int   g_rowptr[MAXN + 2];
__device__ __align__(16) float g_dis[MAXN];
__device__ __align__(16) int   g_bsum[MAX_SCAN_BLOCKS + 1];
__device__ __align__(16) int   g_col[MAXE];
__device__ __align__(16) float g_w[MAXE];
__device__ __align__(16) float g_h1[(size_t)MAXN * 128];
__device__ __align__(16) float g_h2[(size_t)MAXN * 128];

__device__ __forceinline__ const float* buf_in(int sel)  { return sel == 0 ? g_h1 : g_h2; }
__device__ __forceinline__ float*       buf_out(int sel) { return sel == 0 ? g_h1 : g_h2; }

// ---------------- preprocessing -------------------------------------------
__global__ void k_zero(int n) {
    int i = blockIdx.x * blockDim.x + threadIdx.x;
    if (i < n) { g_deg[i] = 0; g_cursor[i] = 0; }
}

__global__ void k_count(const int* __restrict__ dst, int E, int n) {
    int i = blockIdx.x * blockDim.x + threadIdx.x;
    if (i < E) {
        unsigned d = (unsigned)dst[i];
        if (d < (unsigned)n) atomicAdd(&g_deg[d], 1);
    }
}

__global__ void k_dis(int n) {
    int i = blockIdx.x * blockDim.x + threadIdx.x;
    if (i < n) g_dis[i] = rsqrtf((float)(g_deg[i] + 1));  // +1 self loop
}

// -------- 3-phase multi-block exclusive scan of g_deg -> g_rowptr ----------
// Phase A: per-block sums
__global__ void k_scanA(int n) {
    __shared__ int sh[SCAN_B];
    int i = blockIdx.x * SCAN_B + threadIdx.x;
    int v = (i < n) ? g_deg[i] : 0;
    sh[threadIdx.x] = v;
    __syncthreads();
    for (int off = SCAN_B / 2; off > 0; off >>= 1) {
        if (threadIdx.x < off) sh[threadIdx.x] += sh[threadIdx.x + off];
        __syncthreads();
    }
    if (threadIdx.x == 0) g_bsum[blockIdx.x] = sh[0];
}

// Phase B: single small block scans the 196 block sums (exclusive, in place)
__global__ void k_scanB(int nblocks, int n) {
    __shared__ int sh[SCAN_B];
    int t = threadIdx.x;
    int v = (t < nblocks) ? g_bsum[t] : 0;
    sh[t] = v;
    __syncthreads();
    // Hillis-Steele inclusive
    for (int off = 1; off < SCAN_B; off <<= 1) {
        int u = (t >= off) ? sh[t - off] : 0;
        __syncthreads();
        sh[t] += u;
        __syncthreads();
    }
    if (t < nblocks) g_bsum[t] = sh[t] - v;   // exclusive
    if (t == nblocks - 1) g_rowptr[n] = sh[t]; // total
}

// Phase C: per-block exclusive scan + offset -> g_rowptr
__global__ void k_scanC(int n) {
    __shared__ int sh[SCAN_B];
    int i = blockIdx.x * SCAN_B + threadIdx.x;
    int t = threadIdx.x;
    int v = (i < n) ? g_deg[i] : 0;
    sh[t] = v;
    __syncthreads();
    for (int off = 1; off < SCAN_B; off <<= 1) {
        int u = (t >= off) ? sh[t - off] : 0;
        __syncthreads();
        sh[t] += u;
        __syncthreads();
    }
    if (i < n) g_rowptr[i] = sh[t] - v + g_bsum[blockIdx.x];
}

__global__ void k_fill(const int* __restrict__ src,
                       const int* __restrict__ dst, int E, int n) {
    int i = blockIdx.x * blockDim.x + threadIdx.x;
    if (i < E) {
        unsigned s = (unsigned)src[i];
        unsigned d = (unsigned)dst[i];
        if (s < (unsigned)n && d < (unsigned)n) {
            int pos = g_rowptr[d] + atomicAdd(&g_cursor[d], 1);
            g_col[pos] = (int)s;
            g_w[pos] = g_dis[s] * g_dis[d];
        }
    }
}

// ---------------- aggregation: one warp per node ----------------------------
// out[i] = dis[i]^2 * in[i] + sum_j w_j * in[col_j]
// Edge indices/weights loaded 32-wide (coalesced) then shfl-broadcast:
// removes the serial dependent lane-uniform loads; row gathers pipeline.

__global__ void k_agg128(int n) {
    int warp = (blockIdx.x * blockDim.x + threadIdx.x) >> 5;
    int lane = threadIdx.x & 31;
    if (warp >= n) return;
    const float* in = g_h2;
    float ds = g_dis[warp];
    float self = ds * ds;
    float4 v = ((const float4*)(in + (size_t)warp * 128))[lane];
    float4 acc = make_float4(self * v.x, self * v.y, self * v.z, self * v.w);
    int beg = g_rowptr[warp], end = g_rowptr[warp + 1];
    for (int base = beg; base < end; base += 32) {
        int idx = base + lane;
        int c = 0; float wv = 0.f;
        if (idx < end) { c = g_col[idx]; wv = g_w[idx]; }
        int m = min(32, end - base);
        for (int t = 0; t < m; t++) {
            int s   = __shfl_sync(0xffffffffu, c, t);
            float w = __shfl_sync(0xffffffffu, wv, t);
            float4 u = ((const float4*)(in + (size_t)s * 128))[lane];
            acc.x += w * u.x; acc.y += w * u.y; acc.z += w * u.z; acc.w += w * u.w;
        }
    }
    ((float4*)(g_h1 + (size_t)warp * 128))[lane] = acc;
}

__global__ void k_agg64_first(const float* __restrict__ in, int n) {
    int warp = (blockIdx.x * blockDim.x + threadIdx.x) >> 5;
    int lane = threadIdx.x & 31;
    if (warp >= n) return;
    float ds = g_dis[warp];
    float self = ds * ds;
    float2 v = ((const float2*)(in + (size_t)warp * 64))[lane];
    float2 acc = make_float2(self * v.x, self * v.y);
    int beg = g_rowptr[warp], end = g_rowptr[warp + 1];
    for (int base = beg; base < end; base += 32) {
        int idx = base + lane;
        int c = 0; float wv = 0.f;
        if (idx < end) { c = g_col[idx]; wv = g_w[idx]; }
        int m = min(32, end - base);
        for (int t = 0; t < m; t++) {
            int s   = __shfl_sync(0xffffffffu, c, t);
            float w = __shfl_sync(0xffffffffu, wv, t);
            float2 u = ((const float2*)(in + (size_t)s * 64))[lane];
            acc.x += w * u.x; acc.y += w * u.y;
        }
    }
    ((float2*)(g_h1 + (size_t)warp * 64))[lane] = acc;
}

__global__ void k_agg64_last(float* __restrict__ out,
                             const float* __restrict__ bias, int n) {
    int warp = (blockIdx.x * blockDim.x + threadIdx.x) >> 5;
    int lane = threadIdx.x & 31;
    if (warp >= n) return;
    const float* in = g_h1;
    float ds = g_dis[warp];
    float self = ds * ds;
    float2 v = ((const float2*)(in + (size_t)warp * 64))[lane];
    float2 acc = make_float2(self * v.x, self * v.y);
    int beg = g_rowptr[warp], end = g_rowptr[warp + 1];
    for (int base = beg; base < end; base += 32) {
        int idx = base + lane;
        int c = 0; float wv = 0.f;
        if (idx < end) { c = g_col[idx]; wv = g_w[idx]; }
        int m = min(32, end - base);
        for (int t = 0; t < m; t++) {
            int s   = __shfl_sync(0xffffffffu, c, t);
            float w = __shfl_sync(0xffffffffu, wv, t);
            float2 u = ((const float2*)(in + (size_t)s * 64))[lane];
            acc.x += w * u.x; acc.y += w * u.y;
        }
    }
    acc.x += bias[lane * 2];
    acc.y += bias[lane * 2 + 1];
    ((float2*)(out + (size_t)warp * 64))[lane] = acc;
}

// ---------------- 2D register-tiled GEMM ------------------------------------
// Y[n,OUT] = X[n,IN] @ W[IN,OUT] (+bias)(+relu). 128xOUT block, 16x16 threads,
// each thread computes an 8 x (OUT/16) micro-tile. K staged in 16-chunks.
template <int IN, int OUT, bool BIAS, bool RELU>
__global__ void k_gemm(int insel, int outsel,
                       const float* __restrict__ Wm,
                       const float* __restrict__ bias, int n) {
    constexpr int TM = 128, TK = 16;
    constexpr int RT = 8;             // rows per thread
    constexpr int CT = OUT / 16;      // cols per thread: 8 or 4
    constexpr int LDX = TM + 1;       // pad to break write conflicts
    __shared__ float Xs[TK][LDX];     // transposed: Xs[k][row]
    __shared__ float Ws[TK][OUT];

    const float* X = buf_in(insel);
    float* Y = buf_out(outsel);

    int tid = threadIdx.x;
    int tx = tid & 15;                // col group
    int ty = tid >> 4;                // row group
    int row0 = blockIdx.x * TM;

    float acc[RT][CT];
#pragma unroll
    for (int i = 0; i < RT; i++)
#pragma unroll
        for (int j = 0; j < CT; j++) acc[i][j] = 0.f;

    for (int k0 = 0; k0 < IN; k0 += TK) {
        // load X tile (TM x TK), store transposed
#pragma unroll
        for (int e = 0; e < (TM * TK) / 256; e++) {
            int idx = tid + e * 256;
            int r = idx / TK, k = idx % TK;
            int gr = row0 + r;
            Xs[k][r] = (gr < n) ? X[(size_t)gr * IN + k0 + k] : 0.f;
        }
        // load W tile (TK x OUT), straight copy (coalesced)
#pragma unroll
        for (int e = 0; e < (TK * OUT) / 256; e++) {
            int idx = tid + e * 256;
            int k = idx / OUT, c = idx % OUT;
            Ws[k][c] = Wm[(size_t)(k0 + k) * OUT + c];
        }
        __syncthreads();

#pragma unroll
        for (int kk = 0; kk < TK; kk++) {
            float a[RT], b[CT];
#pragma unroll
            for (int i = 0; i < RT; i++) a[i] = Xs[kk][ty * RT + i];
#pragma unroll
            for (int j = 0; j < CT; j++) b[j] = Ws[kk][tx * CT + j];
#pragma unroll
            for (int i = 0; i < RT; i++)
#pragma unroll
                for (int j = 0; j < CT; j++)
                    acc[i][j] += a[i] * b[j];
        }
        __syncthreads();
    }

#pragma unroll
    for (int i = 0; i < RT; i++) {
        int r = row0 + ty * RT + i;
        if (r < n) {
#pragma unroll
            for (int j = 0; j < CT; j++) {
                int c = tx * CT + j;
                float v = acc[i][j];
                if (BIAS) v += __ldg(&bias[c]);
                if (RELU) v = fmaxf(v, 0.f);
                Y[(size_t)r * OUT + c] = v;
            }
        }
    }
}

// ---------------- launch ----------------------------------------------------
extern "C" void kernel_launch(void* const* d_in, const int* in_sizes, int n_in,
                              void* d_out, int out_size) {
    const float* x  = (const float*)d_in[0];
    const int*   ei = (const int*)d_in[1];   // int32 (JAX x64 disabled)
    const float* W1 = (const float*)d_in[2];
    const float* b1 = (const float*)d_in[3];
    const float* W2 = (const float*)d_in[4];
    const float* b2 = (const float*)d_in[5];
    const float* W3 = (const float*)d_in[6];
    const float* b3 = (const float*)d_in[7];
    float* out = (float*)d_out;

    const int n = in_sizes[0] / 64;   // 50000
    const int E = in_sizes[1] / 2;    // 800000
    const int* src = ei;
    const int* dst = ei + E;

    const int T = 256;
    const int scanBlocks = (n + SCAN_B - 1) / SCAN_B;   // 196

    // --- build CSR + normalization ---
    k_zero<<<(n + T - 1) / T, T>>>(n);
    k_count<<<(E + T - 1) / T, T>>>(dst, E, n);
    k_dis<<<(n + T - 1) / T, T>>>(n);
    k_scanA<<<scanBlocks, SCAN_B>>>(n);
    k_scanB<<<1, SCAN_B>>>(scanBlocks, n);
    k_scanC<<<scanBlocks, SCAN_B>>>(n);
    k_fill<<<(E + T - 1) / T, T>>>(src, dst, E, n);

    const int aggGrid = (n + 7) / 8;  // 8 warps per block (256 threads)
    const int gemmGrid = (n + 127) / 128;

    // Layer 1: (A x)[64] @ W1 -> relu -> g_h2[128]
    k_agg64_first<<<aggGrid, T>>>(x, n);                                   // x -> g_h1
    k_gemm<64, 128, true, true><<<gemmGrid, T>>>(0, 1, W1, b1, n);         // g_h1 -> g_h2

    // Layer 2: (A g_h2)[128] @ W2 -> relu -> g_h2[128]
    k_agg128<<<aggGrid, T>>>(n);                                           // g_h2 -> g_h1
    k_gemm<128, 128, true, true><<<gemmGrid, T>>>(0, 1, W2, b2, n);        // g_h1 -> g_h2

    // Layer 3: (g_h2 @ W3)[64] -> aggregate -> + b3 -> out
    k_gemm<128, 64, false, false><<<gemmGrid, T>>>(1, 0, W3, nullptr, n);  // g_h2 -> g_h1
    k_agg64_last<<<aggGrid, T>>>(out, b3, n);                              // g_h1 -> out
}

// round 7
// speedup vs baseline: 1.7551x; 1.2267x over previous
#include <cuda_runtime.h>
#include <cuda_bf16.h>
#include <cstdint>

#define MAXN 50000
#define MAXE 800000
#define SCAN_B 256
#define MAX_SCAN_BLOCKS ((MAXN + SCAN_B - 1) / SCAN_B)   // 196

// ---------------- scratch (device globals: no allocation allowed) ----------
__device__ __align__(16) int   g_deg[MAXN];
__device__ __align__(16) int   g_cursor[MAXN];
__device__ __align__(16) int   g_rowptr[MAXN + 2];
__device__ __align__(16) float g_dis[MAXN];
__device__ __align__(16) int   g_bsum[MAX_SCAN_BLOCKS + 1];
__device__ __align__(16) int   g_col[MAXE];
__device__ __align__(16) float g_w[MAXE];
__device__ __align__(16) float g_h1[(size_t)MAXN * 128];
__device__ __align__(16) float g_h2[(size_t)MAXN * 128];
// tf32 hi/lo W fragments, pre-arranged in mma fragment order:
// L1 hi@0 lo@8192 | L2 hi@16384 lo@32768 | L3 hi@49152 lo@57344
__device__ __align__(16) float g_wfrag[65536];

__device__ __forceinline__ const float* buf_in(int sel)  { return sel == 0 ? g_h1 : g_h2; }
__device__ __forceinline__ float*       buf_out(int sel) { return sel == 0 ? g_h1 : g_h2; }

// tf32 destination must be a .b32 register in PTX (not .f32)
__device__ __forceinline__ float tf32_rna(float x) {
    unsigned r;
    asm("cvt.rna.tf32.f32 %0, %1;" : "=r"(r) : "f"(x));
    return __uint_as_float(r);
}

// D += A(16x8) * B(8x8), tf32 inputs, f32 accum.
// A0 = (row g: k=t, k=t+4), A1 = (row g+8: k=t, k=t+4), B = (k=t, k=t+4) for col g.
__device__ __forceinline__ void mma_tf32(float c[4], float2 A0, float2 A1, float2 B) {
    asm volatile(
        "mma.sync.aligned.m16n8k8.row.col.f32.tf32.tf32.f32 "
        "{%0,%1,%2,%3}, {%4,%5,%6,%7}, {%8,%9}, {%0,%1,%2,%3};"
        : "+f"(c[0]), "+f"(c[1]), "+f"(c[2]), "+f"(c[3])
        : "r"(__float_as_uint(A0.x)), "r"(__float_as_uint(A1.x)),
          "r"(__float_as_uint(A0.y)), "r"(__float_as_uint(A1.y)),
          "r"(__float_as_uint(B.x)),  "r"(__float_as_uint(B.y)));
}

// ---------------- preprocessing -------------------------------------------
__global__ void k_zero(int n) {
    int i = blockIdx.x * blockDim.x + threadIdx.x;
    if (i < n) { g_deg[i] = 0; g_cursor[i] = 0; }
}

__global__ void k_count(const int* __restrict__ dst, int E, int n) {
    int i = blockIdx.x * blockDim.x + threadIdx.x;
    if (i < E) {
        unsigned d = (unsigned)dst[i];
        if (d < (unsigned)n) atomicAdd(&g_deg[d], 1);
    }
}

__global__ void k_dis(int n) {
    int i = blockIdx.x * blockDim.x + threadIdx.x;
    if (i < n) g_dis[i] = rsqrtf((float)(g_deg[i] + 1));  // +1 self loop
}

// W -> tf32 hi/lo fragments (fragment-order layout).
// frag offset for (k, n): ((kc*2+kk)*OUT + n)*8 + t*2 + slot,
//   kc = k/16, kk = (k%16)/8, t = k%4, slot = (k%8)/4.
__global__ void k_wprep(const float* __restrict__ W1,
                        const float* __restrict__ W2,
                        const float* __restrict__ W3) {
    int i = blockIdx.x * blockDim.x + threadIdx.x;   // 0..32767
    if (i >= 32768) return;
    const float* W; int OUT, base, rel, inout;
    if (i < 8192)       { W = W1; OUT = 128; base = 0;     rel = i;         inout = 8192; }
    else if (i < 24576) { W = W2; OUT = 128; base = 16384; rel = i - 8192;  inout = 16384; }
    else                { W = W3; OUT = 64;  base = 49152; rel = i - 24576; inout = 8192; }
    int k = rel / OUT, n = rel % OUT;
    float w = W[rel];
    float hi = tf32_rna(w);
    float lo = tf32_rna(w - hi);
    int t = k & 3, slot = (k >> 2) & 1;
    int kc = k >> 4, kk = (k >> 3) & 1;
    int off = (((kc * 2 + kk) * OUT + n) << 3) + (t << 1) + slot;
    g_wfrag[base + off] = hi;
    g_wfrag[base + inout + off] = lo;
}

// -------- 3-phase multi-block exclusive scan of g_deg -> g_rowptr ----------
__global__ void k_scanA(int n) {
    __shared__ int sh[SCAN_B];
    int i = blockIdx.x * SCAN_B + threadIdx.x;
    int v = (i < n) ? g_deg[i] : 0;
    sh[threadIdx.x] = v;
    __syncthreads();
    for (int off = SCAN_B / 2; off > 0; off >>= 1) {
        if (threadIdx.x < off) sh[threadIdx.x] += sh[threadIdx.x + off];
        __syncthreads();
    }
    if (threadIdx.x == 0) g_bsum[blockIdx.x] = sh[0];
}

__global__ void k_scanB(int nblocks, int n) {
    __shared__ int sh[SCAN_B];
    int t = threadIdx.x;
    int v = (t < nblocks) ? g_bsum[t] : 0;
    sh[t] = v;
    __syncthreads();
    for (int off = 1; off < SCAN_B; off <<= 1) {
        int u = (t >= off) ? sh[t - off] : 0;
        __syncthreads();
        sh[t] += u;
        __syncthreads();
    }
    if (t < nblocks) g_bsum[t] = sh[t] - v;
    if (t == nblocks - 1) g_rowptr[n] = sh[t];
}

__global__ void k_scanC(int n) {
    __shared__ int sh[SCAN_B];
    int i = blockIdx.x * SCAN_B + threadIdx.x;
    int t = threadIdx.x;
    int v = (i < n) ? g_deg[i] : 0;
    sh[t] = v;
    __syncthreads();
    for (int off = 1; off < SCAN_B; off <<= 1) {
        int u = (t >= off) ? sh[t - off] : 0;
        __syncthreads();
        sh[t] += u;
        __syncthreads();
    }
    if (i < n) g_rowptr[i] = sh[t] - v + g_bsum[blockIdx.x];
}

__global__ void k_fill(const int* __restrict__ src,
                       const int* __restrict__ dst, int E, int n) {
    int i = blockIdx.x * blockDim.x + threadIdx.x;
    if (i < E) {
        unsigned s = (unsigned)src[i];
        unsigned d = (unsigned)dst[i];
        if (s < (unsigned)n && d < (unsigned)n) {
            int pos = g_rowptr[d] + atomicAdd(&g_cursor[d], 1);
            g_col[pos] = (int)s;
            g_w[pos] = g_dis[s] * g_dis[d];
        }
    }
}

// ---------------- aggregation: one warp per node ----------------------------
__global__ void k_agg128(int n) {
    int warp = (blockIdx.x * blockDim.x + threadIdx.x) >> 5;
    int lane = threadIdx.x & 31;
    if (warp >= n) return;
    const float* in = g_h2;
    float ds = g_dis[warp];
    float self = ds * ds;
    float4 v = ((const float4*)(in + (size_t)warp * 128))[lane];
    float4 acc = make_float4(self * v.x, self * v.y, self * v.z, self * v.w);
    int beg = g_rowptr[warp], end = g_rowptr[warp + 1];
    for (int base = beg; base < end; base += 32) {
        int idx = base + lane;
        int c = 0; float wv = 0.f;
        if (idx < end) { c = g_col[idx]; wv = g_w[idx]; }
        int m = min(32, end - base);
        for (int t = 0; t < m; t++) {
            int s   = __shfl_sync(0xffffffffu, c, t);
            float w = __shfl_sync(0xffffffffu, wv, t);
            float4 u = ((const float4*)(in + (size_t)s * 128))[lane];
            acc.x += w * u.x; acc.y += w * u.y; acc.z += w * u.z; acc.w += w * u.w;
        }
    }
    ((float4*)(g_h1 + (size_t)warp * 128))[lane] = acc;
}

__global__ void k_agg64_first(const float* __restrict__ in, int n) {
    int warp = (blockIdx.x * blockDim.x + threadIdx.x) >> 5;
    int lane = threadIdx.x & 31;
    if (warp >= n) return;
    float ds = g_dis[warp];
    float self = ds * ds;
    float2 v = ((const float2*)(in + (size_t)warp * 64))[lane];
    float2 acc = make_float2(self * v.x, self * v.y);
    int beg = g_rowptr[warp], end = g_rowptr[warp + 1];
    for (int base = beg; base < end; base += 32) {
        int idx = base + lane;
        int c = 0; float wv = 0.f;
        if (idx < end) { c = g_col[idx]; wv = g_w[idx]; }
        int m = min(32, end - base);
        for (int t = 0; t < m; t++) {
            int s   = __shfl_sync(0xffffffffu, c, t);
            float w = __shfl_sync(0xffffffffu, wv, t);
            float2 u = ((const float2*)(in + (size_t)s * 64))[lane];
            acc.x += w * u.x; acc.y += w * u.y;
        }
    }
    ((float2*)(g_h1 + (size_t)warp * 64))[lane] = acc;
}

__global__ void k_agg64_last(float* __restrict__ out,
                             const float* __restrict__ bias, int n) {
    int warp = (blockIdx.x * blockDim.x + threadIdx.x) >> 5;
    int lane = threadIdx.x & 31;
    if (warp >= n) return;
    const float* in = g_h1;
    float ds = g_dis[warp];
    float self = ds * ds;
    float2 v = ((const float2*)(in + (size_t)warp * 64))[lane];
    float2 acc = make_float2(self * v.x, self * v.y);
    int beg = g_rowptr[warp], end = g_rowptr[warp + 1];
    for (int base = beg; base < end; base += 32) {
        int idx = base + lane;
        int c = 0; float wv = 0.f;
        if (idx < end) { c = g_col[idx]; wv = g_w[idx]; }
        int m = min(32, end - base);
        for (int t = 0; t < m; t++) {
            int s   = __shfl_sync(0xffffffffu, c, t);
            float w = __shfl_sync(0xffffffffu, wv, t);
            float2 u = ((const float2*)(in + (size_t)s * 64))[lane];
            acc.x += w * u.x; acc.y += w * u.y;
        }
    }
    acc.x += bias[lane * 2];
    acc.y += bias[lane * 2 + 1];
    ((float2*)(out + (size_t)warp * 64))[lane] = acc;
}

// ---------------- tensor-core GEMM (3xTF32) ---------------------------------
// Y[n,OUT] = X[n,IN] @ W[IN,OUT] (+bias)(+relu).
// Block: 128 threads (4 warps), tile 128 rows; warp w -> rows [w*32, w*32+32).
// K staged in 16-chunks; fragments pre-arranged: XF[kk][r][t][2], WF[kk][n][t][2].
template <int IN, int OUT, bool BIAS, bool RELU>
__global__ void __launch_bounds__(128) k_gemm_tc(int insel, int outsel,
        const float* __restrict__ bias, int wfb, int n) {
    constexpr int NT = OUT / 8;
    __shared__ float XFh[2 * 128 * 8];
    __shared__ float XFl[2 * 128 * 8];
    __shared__ float WFh[2 * OUT * 8];
    __shared__ float WFl[2 * OUT * 8];

    const float* X = buf_in(insel);
    float* Y = buf_out(outsel);
    const float* WH = g_wfrag + wfb;
    const float* WL = WH + IN * OUT;

    int tid = threadIdx.x;
    int w = tid >> 5, lane = tid & 31, g = lane >> 2, t = lane & 3;
    int row0 = blockIdx.x * 128;

    float acc[2][NT][4];
#pragma unroll
    for (int m = 0; m < 2; m++)
#pragma unroll
        for (int nt = 0; nt < NT; nt++)
#pragma unroll
            for (int q = 0; q < 4; q++) acc[m][nt][q] = 0.f;

    for (int kc = 0; kc < IN / 16; kc++) {
        // ---- stage X chunk: 128 rows x 16 k = 512 float4 loads ----
#pragma unroll
        for (int f = 0; f < 4; f++) {
            int fid = tid + f * 128;      // 0..511
            int r = fid >> 2;
            int j = fid & 3;              // float4 index within row chunk
            float4 v = make_float4(0.f, 0.f, 0.f, 0.f);
            int gr = row0 + r;
            if (gr < n) v = *(const float4*)(X + (size_t)gr * IN + kc * 16 + j * 4);
            int kk = j >> 1, slot = j & 1;
            int b = kk * 1024 + r * 8 + slot;
            float h0 = tf32_rna(v.x), h1 = tf32_rna(v.y);
            float h2 = tf32_rna(v.z), h3 = tf32_rna(v.w);
            XFh[b + 0] = h0; XFh[b + 2] = h1; XFh[b + 4] = h2; XFh[b + 6] = h3;
            XFl[b + 0] = tf32_rna(v.x - h0); XFl[b + 2] = tf32_rna(v.y - h1);
            XFl[b + 4] = tf32_rna(v.z - h2); XFl[b + 6] = tf32_rna(v.w - h3);
        }
        // ---- stage W chunk: contiguous OUT*16 floats each ----
        {
            const float4* sh_ = (const float4*)(WH + kc * OUT * 16);
            const float4* sl_ = (const float4*)(WL + kc * OUT * 16);
            float4* dh = (float4*)WFh;
            float4* dl = (float4*)WFl;
            for (int f = tid; f < OUT * 4; f += 128) { dh[f] = sh_[f]; dl[f] = sl_[f]; }
        }
        __syncthreads();

#pragma unroll
        for (int kk = 0; kk < 2; kk++) {
            float2 ah[2][2], al[2][2];
#pragma unroll
            for (int m = 0; m < 2; m++) {
                int r = w * 32 + m * 16 + g;
                ah[m][0] = *(const float2*)(XFh + kk * 1024 + r * 8 + t * 2);
                ah[m][1] = *(const float2*)(XFh + kk * 1024 + (r + 8) * 8 + t * 2);
                al[m][0] = *(const float2*)(XFl + kk * 1024 + r * 8 + t * 2);
                al[m][1] = *(const float2*)(XFl + kk * 1024 + (r + 8) * 8 + t * 2);
            }
#pragma unroll
            for (int nt = 0; nt < NT; nt++) {
                int nb = kk * OUT * 8 + (nt * 8 + g) * 8 + t * 2;
                float2 bh = *(const float2*)(WFh + nb);
                float2 bl = *(const float2*)(WFl + nb);
#pragma unroll
                for (int m = 0; m < 2; m++) {
                    mma_tf32(acc[m][nt], ah[m][0], ah[m][1], bh);  // hi*hi
                    mma_tf32(acc[m][nt], ah[m][0], ah[m][1], bl);  // hi*lo
                    mma_tf32(acc[m][nt], al[m][0], al[m][1], bh);  // lo*hi
                }
            }
        }
        __syncthreads();
    }

    // ---- epilogue ----
#pragma unroll
    for (int m = 0; m < 2; m++) {
        int r = row0 + w * 32 + m * 16 + g;
#pragma unroll
        for (int nt = 0; nt < NT; nt++) {
            int c = nt * 8 + t * 2;
            float2 p0 = make_float2(acc[m][nt][0], acc[m][nt][1]);
            float2 p1 = make_float2(acc[m][nt][2], acc[m][nt][3]);
            if (BIAS) {
                float2 bb = *(const float2*)(bias + c);
                p0.x += bb.x; p0.y += bb.y; p1.x += bb.x; p1.y += bb.y;
            }
            if (RELU) {
                p0.x = fmaxf(p0.x, 0.f); p0.y = fmaxf(p0.y, 0.f);
                p1.x = fmaxf(p1.x, 0.f); p1.y = fmaxf(p1.y, 0.f);
            }
            if (r < n)     *(float2*)(Y + (size_t)r * OUT + c) = p0;
            if (r + 8 < n) *(float2*)(Y + (size_t)(r + 8) * OUT + c) = p1;
        }
    }
}

// ---------------- launch ----------------------------------------------------
extern "C" void kernel_launch(void* const* d_in, const int* in_sizes, int n_in,
                              void* d_out, int out_size) {
    const float* x  = (const float*)d_in[0];
    const int*   ei = (const int*)d_in[1];   // int32 (JAX x64 disabled)
    const float* W1 = (const float*)d_in[2];
    const float* b1 = (const float*)d_in[3];
    const float* W2 = (const float*)d_in[4];
    const float* b2 = (const float*)d_in[5];
    const float* W3 = (const float*)d_in[6];
    const float* b3 = (const float*)d_in[7];
    float* out = (float*)d_out;

    const int n = in_sizes[0] / 64;   // 50000
    const int E = in_sizes[1] / 2;    // 800000
    const int* src = ei;
    const int* dst = ei + E;

    const int T = 256;
    const int scanBlocks = (n + SCAN_B - 1) / SCAN_B;   // 196

    // --- build CSR + normalization + W fragments ---
    k_zero<<<(n + T - 1) / T, T>>>(n);
    k_count<<<(E + T - 1) / T, T>>>(dst, E, n);
    k_wprep<<<128, 256>>>(W1, W2, W3);
    k_dis<<<(n + T - 1) / T, T>>>(n);
    k_scanA<<<scanBlocks, SCAN_B>>>(n);
    k_scanB<<<1, SCAN_B>>>(scanBlocks, n);
    k_scanC<<<scanBlocks, SCAN_B>>>(n);
    k_fill<<<(E + T - 1) / T, T>>>(src, dst, E, n);

    const int aggGrid = (n + 7) / 8;      // 8 warps/block
    const int gemmGrid = (n + 127) / 128; // 391

    // Layer 1: (A x)[64] @ W1 -> relu -> g_h2[128]
    k_agg64_first<<<aggGrid, T>>>(x, n);
    k_gemm_tc<64, 128, true, true><<<gemmGrid, 128>>>(0, 1, b1, 0, n);

    // Layer 2: (A g_h2)[128] @ W2 -> relu -> g_h2[128]
    k_agg128<<<aggGrid, T>>>(n);
    k_gemm_tc<128, 128, true, true><<<gemmGrid, 128>>>(0, 1, b2, 16384, n);

    // Layer 3: (g_h2 @ W3)[64] -> aggregate -> + b3 -> out
    k_gemm_tc<128, 64, false, false><<<gemmGrid, 128>>>(1, 0, nullptr, 49152, n);
    k_agg64_last<<<aggGrid, T>>>(out, b3, n);
}